// round 2
// baseline (speedup 1.0000x reference)
#include <cuda_runtime.h>
#include <cstdint>

// Problem constants
#define Bsz 16
#define Jn  16
#define Cn  64
#define HW  65536              // 256*256
#define HW4 16384              // float4s per channel
#define NCH (Bsz * Jn)         // 256 heatmap channels
#define TPB 256
#define NCTA 296               // 2 CTAs per SM on 148 SMs -> perfectly balanced
#define TOTF4 (NCH * HW4)      // 4194304 total float4s
#define CHUNK ((TOTF4 + NCTA - 1) / NCTA)  // 14170

// Scratch (device globals: allocation-free). Zero-initialized at module load;
// every completer resets its slots so graph replays see a clean state.
__device__ unsigned long long g_pack[NCH];   // packed (orderable(val) << 32) | (~idx)
__device__ int                g_cnt[NCH];    // float4s accumulated per channel
__device__ float              g_joint[NCH];  // per-(b,j) sum of squared errors over C
__device__ int                g_bcnt[Bsz];   // joints completed per batch

// Monotonic float -> uint mapping (order-preserving for max)
__device__ __forceinline__ unsigned ordf(float f) {
    unsigned u = __float_as_uint(f);
    return (u & 0x80000000u) ? ~u : (u | 0x80000000u);
}

__global__ __launch_bounds__(TPB, 2)
void fused_label_loss(const float* __restrict__ heatmap,
                      const float* __restrict__ pred,
                      const float* __restrict__ gt,
                      float* __restrict__ out)
{
    const int tid = threadIdx.x;
    const int f0 = blockIdx.x * CHUNK;
    const int f1 = min(f0 + CHUNK, TOTF4);

    __shared__ float sv[TPB];
    __shared__ int   si[TPB];
    __shared__ int   s_complete;
    __shared__ int   s_idx;
    __shared__ float s_warp[2];

    const float4* hm4 = reinterpret_cast<const float4*>(heatmap);

    int pos = f0;
    while (pos < f1) {
        const int ch     = pos / HW4;
        const int chbase = ch * HW4;
        const int chend  = min(f1, chbase + HW4);

        // ---- local argmax over this CTA's segment of channel ch ----
        float bv = -3.402823466e+38f;
        int   bi = 0x7FFFFFFF;
        #pragma unroll 4
        for (int i = pos + tid; i < chend; i += TPB) {
            float4 v = hm4[i];
            int base = (i - chbase) * 4;
            if (v.x > bv) { bv = v.x; bi = base;     } else if (v.x == bv && base     < bi) bi = base;
            if (v.y > bv) { bv = v.y; bi = base + 1; } else if (v.y == bv && base + 1 < bi) bi = base + 1;
            if (v.z > bv) { bv = v.z; bi = base + 2; } else if (v.z == bv && base + 2 < bi) bi = base + 2;
            if (v.w > bv) { bv = v.w; bi = base + 3; } else if (v.w == bv && base + 3 < bi) bi = base + 3;
        }

        sv[tid] = bv; si[tid] = bi;
        __syncthreads();
        for (int s = TPB / 2; s > 0; s >>= 1) {
            if (tid < s) {
                float ov = sv[tid + s];
                int   oi = si[tid + s];
                if (ov > sv[tid] || (ov == sv[tid] && oi < si[tid])) {
                    sv[tid] = ov; si[tid] = oi;
                }
            }
            __syncthreads();
        }

        // ---- publish segment result; detect channel completion by byte count ----
        if (tid == 0) {
            unsigned long long pk =
                ((unsigned long long)ordf(sv[0]) << 32) |
                (unsigned long long)(0xFFFFFFFFu - (unsigned)si[0]);
            atomicMax(&g_pack[ch], pk);
            __threadfence();
            const int n   = chend - pos;
            const int old = atomicAdd(&g_cnt[ch], n);
            if (old + n == HW4) {
                __threadfence();
                unsigned long long fin =
                    *(volatile unsigned long long*)&g_pack[ch];
                s_idx = (int)(0xFFFFFFFFu - (unsigned)(fin & 0xFFFFFFFFull));
                s_complete = 1;
                g_pack[ch] = 0;   // reset for next graph replay
                g_cnt[ch]  = 0;
            } else {
                s_complete = 0;
            }
        }
        __syncthreads();

        // ---- channel completer: gather pred at idx, MSE over C ----
        if (s_complete) {
            const int idx = s_idx;
            const int b = ch >> 4;
            float acc = 0.f;
            if (tid < Cn) {
                float p = pred[((size_t)(b * Cn + tid)) * HW + idx];
                float g = gt[(size_t)ch * Cn + tid];   // (b*Jn + j)*Cn == ch*Cn
                float d = p - g;
                acc = d * d;
                #pragma unroll
                for (int off = 16; off > 0; off >>= 1)
                    acc += __shfl_xor_sync(0xFFFFFFFFu, acc, off);
                if ((tid & 31) == 0) s_warp[tid >> 5] = acc;
            }
            __syncthreads();
            if (tid == 0) {
                g_joint[ch] = s_warp[0] + s_warp[1];
                __threadfence();
                const int ob = atomicAdd(&g_bcnt[b], 1);
                if (ob == Jn - 1) {
                    g_bcnt[b] = 0;      // reset for next replay
                    __threadfence();
                    float tot = 0.f;
                    #pragma unroll
                    for (int jj = 0; jj < Jn; ++jj)
                        tot += *(volatile float*)&g_joint[b * Jn + jj];
                    out[b] = tot * (1.0f / (float)(Jn * Cn));
                }
            }
            __syncthreads();
        }

        pos = chend;
    }
}

// ---------------------------------------------------------------------------
extern "C" void kernel_launch(void* const* d_in, const int* in_sizes, int n_in,
                              void* d_out, int out_size)
{
    const float* pred    = (const float*)d_in[0];  // [B,C,H,W]
    const float* gt      = (const float*)d_in[1];  // [B,J,C]
    const float* heatmap = (const float*)d_in[2];  // [B,J,H,W]
    float* out = (float*)d_out;                    // [B]

    fused_label_loss<<<NCTA, TPB>>>(heatmap, pred, gt, out);
}

// round 3
// speedup vs baseline: 1.1892x; 1.1892x over previous
#include <cuda_runtime.h>
#include <cstdint>

// Problem constants
#define Bsz 16
#define Jn  16
#define Cn  64
#define HW  65536              // 256*256
#define HW4 16384              // float4s per channel
#define NCH (Bsz * Jn)         // 256 channels = 256 CTAs
#define TPB 256

// Device-global scratch (allocation-free).
__device__ float g_joint[NCH];   // per-(b,j) sum of squared errors over C
__device__ int   g_bcnt[Bsz];    // joints completed per batch (reset by elected CTA)

__global__ __launch_bounds__(TPB, 8)
void fused_label_loss(const float* __restrict__ heatmap,
                      const float* __restrict__ pred,
                      const float* __restrict__ gt,
                      float* __restrict__ out)
{
    const int ch  = blockIdx.x;          // channel = b*Jn + j
    const int tid = threadIdx.x;

    // ---------------- argmax over heatmap[ch] (first-index tie-break) -------
    const float4* hm = reinterpret_cast<const float4*>(heatmap + (size_t)ch * HW);

    float bv = -3.402823466e+38f;
    int   bi = 0;

    #pragma unroll 4
    for (int i = tid; i < HW4; i += TPB) {
        float4 v = hm[i];
        int base = i * 4;
        if (v.x > bv) { bv = v.x; bi = base;     } else if (v.x == bv && base     < bi) bi = base;
        if (v.y > bv) { bv = v.y; bi = base + 1; } else if (v.y == bv && base + 1 < bi) bi = base + 1;
        if (v.z > bv) { bv = v.z; bi = base + 2; } else if (v.z == bv && base + 2 < bi) bi = base + 2;
        if (v.w > bv) { bv = v.w; bi = base + 3; } else if (v.w == bv && base + 3 < bi) bi = base + 3;
    }

    __shared__ float sv[TPB];
    __shared__ int   si[TPB];
    __shared__ float s_warp[2];
    sv[tid] = bv; si[tid] = bi;
    __syncthreads();

    for (int s = TPB / 2; s > 0; s >>= 1) {
        if (tid < s) {
            float ov = sv[tid + s];
            int   oi = si[tid + s];
            if (ov > sv[tid] || (ov == sv[tid] && oi < si[tid])) {
                sv[tid] = ov; si[tid] = oi;
            }
        }
        __syncthreads();
    }

    // ---------------- fused tail: gather pred @ idx, MSE over C -------------
    const int idx = si[0];               // all threads read after the sync above
    const int b   = ch >> 4;             // ch / Jn

    if (tid < Cn) {
        float p = pred[((size_t)(b * Cn + tid)) * HW + idx];
        float g = gt[(size_t)ch * Cn + tid];          // (b*Jn+j)*Cn == ch*Cn
        float d = p - g;
        float acc = d * d;
        #pragma unroll
        for (int off = 16; off > 0; off >>= 1)
            acc += __shfl_xor_sync(0xFFFFFFFFu, acc, off);
        if ((tid & 31) == 0) s_warp[tid >> 5] = acc;
    }
    __syncthreads();

    if (tid == 0) {
        g_joint[ch] = s_warp[0] + s_warp[1];
        __threadfence();
        const int ob = atomicAdd(&g_bcnt[b], 1);
        if (ob == Jn - 1) {
            g_bcnt[b] = 0;               // reset for next graph replay
            __threadfence();
            // fixed-order sum over joints -> deterministic
            float tot = 0.f;
            #pragma unroll
            for (int jj = 0; jj < Jn; ++jj)
                tot += *(volatile float*)&g_joint[b * Jn + jj];
            out[b] = tot * (1.0f / (float)(Jn * Cn));
        }
    }
}

// ---------------------------------------------------------------------------
extern "C" void kernel_launch(void* const* d_in, const int* in_sizes, int n_in,
                              void* d_out, int out_size)
{
    const float* pred    = (const float*)d_in[0];  // [B,C,H,W]
    const float* gt      = (const float*)d_in[1];  // [B,J,C]
    const float* heatmap = (const float*)d_in[2];  // [B,J,H,W]
    float* out = (float*)d_out;                    // [B]

    fused_label_loss<<<NCH, TPB>>>(heatmap, pred, gt, out);
}